// round 5
// baseline (speedup 1.0000x reference)
#include <cuda_runtime.h>
#include <math.h>

#define BB 8
#define LL 1536
#define HH 8
#define EE 64
#define HE 512          // H*E
#define BHE 4096        // B*H*E
#define TOPK 7          // int(log(1536)) = 7

// ---------------- scratch (static __device__, no allocation) ----------------
__device__ float g_qr[(size_t)BHE * LL];   // layernormed q, (b,h,e,l)
__device__ float g_kr[(size_t)BHE * LL];   // layernormed k, (b,h,e,l)
__device__ float g_mean[BB * LL];          // sum over (h,e) of clipped corr
__device__ float g_scal[4];                // [0]=sigmoid(freq), [1..3]=softmax(scale_weights)
__device__ int   g_delays[BB * TOPK];
__device__ float g_nw[BB * TOPK];

// ---------------- K0: scalars + zero mean accumulator ----------------
__global__ void k0_init(const float* __restrict__ sw, const float* __restrict__ ff) {
    int idx = blockIdx.x * blockDim.x + threadIdx.x;
    for (int i = idx; i < BB * LL; i += gridDim.x * blockDim.x) g_mean[i] = 0.f;
    if (idx == 0) {
        g_scal[0] = 1.f / (1.f + expf(-ff[0]));
        float a = sw[0], b = sw[1], c = sw[2];
        float mx = fmaxf(a, fmaxf(b, c));
        float ea = expf(a - mx), eb = expf(b - mx), ec = expf(c - mx);
        float s = ea + eb + ec;
        g_scal[1] = ea / s; g_scal[2] = eb / s; g_scal[3] = ec / s;
    }
}

// ---------------- K1: LayerNorm over E + transpose to (b,h,e,l) ----------------
__global__ __launch_bounds__(256) void k1_ln(const float* __restrict__ q,
                                             const float* __restrict__ kk) {
    __shared__ float tile[32][EE + 1];
    __shared__ float mu[32], isd[32];
    int l0 = blockIdx.x * 32;
    int bh = blockIdx.y;                 // b*8 + h
    int b  = bh >> 3, h = bh & 7;
    const float* in = blockIdx.z ? kk : q;
    float* out      = blockIdx.z ? g_kr : g_qr;
    int tid = threadIdx.x;
    int e = tid & 63, r0 = tid >> 6;
    for (int r = r0; r < 32; r += 4)
        tile[r][e] = in[(((size_t)b * LL + l0 + r) * HH + h) * EE + e];
    __syncthreads();
    int lane = tid & 31, w = tid >> 5;
    for (int r = w; r < 32; r += 8) {
        float x0 = tile[r][lane], x1 = tile[r][lane + 32];
        float s = x0 + x1, s2 = x0 * x0 + x1 * x1;
        #pragma unroll
        for (int off = 16; off; off >>= 1) {
            s  += __shfl_down_sync(0xffffffffu, s,  off);
            s2 += __shfl_down_sync(0xffffffffu, s2, off);
        }
        if (lane == 0) {
            float m = s * (1.f / EE);
            float v = s2 * (1.f / EE) - m * m;
            mu[r] = m; isd[r] = rsqrtf(v + 1e-5f);
        }
    }
    __syncthreads();
    int li = tid & 31, e0 = tid >> 5;
    for (int ee = e0; ee < EE; ee += 8) {
        float val = (tile[li][ee] - mu[li]) * isd[li];
        out[(((size_t)bh) * EE + ee) * LL + l0 + li] = val;
    }
}

// ---------------- FFT: templated Stockham, SoA + XOR bank swizzle, radix-8 ----
// tw[t] = exp(-2*pi*i*t/1536), t in [0,768). Stage twiddle = tw[j * (1536/(R*L))].
// All FFT buffer indices pass through S(): bijection within each 32-word block,
// breaks power-of-two stride bank patterns.

__device__ __forceinline__ int S(int a) { return a ^ ((a >> 5) & 31); }

template<int R, int M, int L>
__device__ __forceinline__ void fstage(const float* __restrict__ ar, const float* __restrict__ ai,
                                       float* __restrict__ br, float* __restrict__ bi,
                                       const float2* __restrict__ tw, int tid) {
    constexpr int NB   = L * M;            // butterflies; also the input stride
    constexpr int STEP = 1536 / (R * L);
    for (int t = tid; t < NB; t += 256) {
        int j = t / M;                     // compile-time M -> mul/shift
        int k = t - j * M;
        int wb = k + (M * R) * j;
        float2 w1 = tw[j * STEP];
        if (R == 8) {
            float x0r = ar[S(t)],          x0i = ai[S(t)];
            float x1r = ar[S(t + NB)],     x1i = ai[S(t + NB)];
            float x2r = ar[S(t + 2 * NB)], x2i = ai[S(t + 2 * NB)];
            float x3r = ar[S(t + 3 * NB)], x3i = ai[S(t + 3 * NB)];
            float x4r = ar[S(t + 4 * NB)], x4i = ai[S(t + 4 * NB)];
            float x5r = ar[S(t + 5 * NB)], x5i = ai[S(t + 5 * NB)];
            float x6r = ar[S(t + 6 * NB)], x6i = ai[S(t + 6 * NB)];
            float x7r = ar[S(t + 7 * NB)], x7i = ai[S(t + 7 * NB)];
            const float C = 0.70710678118654752f;
            // even half: t_q = x_q + x_{q+4}
            float t0r = x0r + x4r, t0i = x0i + x4i;
            float t1r = x1r + x5r, t1i = x1i + x5i;
            float t2r = x2r + x6r, t2i = x2i + x6i;
            float t3r = x3r + x7r, t3i = x3i + x7i;
            // odd half: u_q = (x_q - x_{q+4}) * W8^q
            float a0r = x0r - x4r, a0i = x0i - x4i;
            float a1r = x1r - x5r, a1i = x1i - x5i;
            float a2r = x2r - x6r, a2i = x2i - x6i;
            float a3r = x3r - x7r, a3i = x3i - x7i;
            float u0r = a0r,                u0i = a0i;
            float u1r = C * (a1r + a1i),    u1i = C * (a1i - a1r);     // * c(1-i)
            float u2r = a2i,                u2i = -a2r;                // * (-i)
            float u3r = C * (a3i - a3r),    u3i = -C * (a3r + a3i);    // * -c(1+i)
            // 4-pt DFT on t -> y0,y2,y4,y6
            float e0r = t0r + t2r, e0i = t0i + t2i;
            float e1r = t0r - t2r, e1i = t0i - t2i;
            float e2r = t1r + t3r, e2i = t1i + t3i;
            float e3r = t1r - t3r, e3i = t1i - t3i;
            float y0r = e0r + e2r, y0i = e0i + e2i;
            float y4r = e0r - e2r, y4i = e0i - e2i;
            float y2r = e1r + e3i, y2i = e1i - e3r;   // e1 - i*e3
            float y6r = e1r - e3i, y6i = e1i + e3r;   // e1 + i*e3
            // 4-pt DFT on u -> y1,y3,y5,y7
            float o0r = u0r + u2r, o0i = u0i + u2i;
            float o1r = u0r - u2r, o1i = u0i - u2i;
            float o2r = u1r + u3r, o2i = u1i + u3i;
            float o3r = u1r - u3r, o3i = u1i - u3i;
            float y1r = o0r + o2r, y1i = o0i + o2i;
            float y5r = o0r - o2r, y5i = o0i - o2i;
            float y3r = o1r + o3i, y3i = o1i - o3r;
            float y7r = o1r - o3i, y7i = o1i + o3r;
            // twiddle powers from w1
            float w2r = w1.x * w1.x - w1.y * w1.y,  w2i = 2.f * w1.x * w1.y;
            float w3r = w2r * w1.x - w2i * w1.y,    w3i = w2r * w1.y + w2i * w1.x;
            float w4r = w2r * w2r - w2i * w2i,      w4i = 2.f * w2r * w2i;
            float w5r = w4r * w1.x - w4i * w1.y,    w5i = w4r * w1.y + w4i * w1.x;
            float w6r = w3r * w3r - w3i * w3i,      w6i = 2.f * w3r * w3i;
            float w7r = w4r * w3r - w4i * w3i,      w7i = w4r * w3i + w4i * w3r;
            br[S(wb)]         = y0r;
            bi[S(wb)]         = y0i;
            br[S(wb + M)]     = y1r * w1.x - y1i * w1.y;
            bi[S(wb + M)]     = y1r * w1.y + y1i * w1.x;
            br[S(wb + 2 * M)] = y2r * w2r - y2i * w2i;
            bi[S(wb + 2 * M)] = y2r * w2i + y2i * w2r;
            br[S(wb + 3 * M)] = y3r * w3r - y3i * w3i;
            bi[S(wb + 3 * M)] = y3r * w3i + y3i * w3r;
            br[S(wb + 4 * M)] = y4r * w4r - y4i * w4i;
            bi[S(wb + 4 * M)] = y4r * w4i + y4i * w4r;
            br[S(wb + 5 * M)] = y5r * w5r - y5i * w5i;
            bi[S(wb + 5 * M)] = y5r * w5i + y5i * w5r;
            br[S(wb + 6 * M)] = y6r * w6r - y6i * w6i;
            bi[S(wb + 6 * M)] = y6r * w6i + y6i * w6r;
            br[S(wb + 7 * M)] = y7r * w7r - y7i * w7i;
            bi[S(wb + 7 * M)] = y7r * w7i + y7i * w7r;
        } else if (R == 4) {
            float c0r = ar[S(t)],          c0i = ai[S(t)];
            float c1r = ar[S(t + NB)],     c1i = ai[S(t + NB)];
            float c2r = ar[S(t + 2 * NB)], c2i = ai[S(t + 2 * NB)];
            float c3r = ar[S(t + 3 * NB)], c3i = ai[S(t + 3 * NB)];
            float t0r = c0r + c2r, t0i = c0i + c2i;
            float t1r = c0r - c2r, t1i = c0i - c2i;
            float t2r = c1r + c3r, t2i = c1i + c3i;
            float t3r = c1r - c3r, t3i = c1i - c3i;
            float d0r = t0r + t2r, d0i = t0i + t2i;
            float d2r = t0r - t2r, d2i = t0i - t2i;
            float d1r = t1r + t3i, d1i = t1i - t3r;   // t1 - i*t3
            float d3r = t1r - t3i, d3i = t1i + t3r;   // t1 + i*t3
            float w2r = w1.x * w1.x - w1.y * w1.y;
            float w2i = 2.f * w1.x * w1.y;
            float w3r = w2r * w1.x - w2i * w1.y;
            float w3i = w2r * w1.y + w2i * w1.x;
            br[S(wb)]         = d0r;
            bi[S(wb)]         = d0i;
            br[S(wb + M)]     = d1r * w1.x - d1i * w1.y;
            bi[S(wb + M)]     = d1r * w1.y + d1i * w1.x;
            br[S(wb + 2 * M)] = d2r * w2r - d2i * w2i;
            bi[S(wb + 2 * M)] = d2r * w2i + d2i * w2r;
            br[S(wb + 3 * M)] = d3r * w3r - d3i * w3i;
            bi[S(wb + 3 * M)] = d3r * w3i + d3i * w3r;
        } else if (R == 3) {
            float c0r = ar[S(t)],          c0i = ai[S(t)];
            float c1r = ar[S(t + NB)],     c1i = ai[S(t + NB)];
            float c2r = ar[S(t + 2 * NB)], c2i = ai[S(t + 2 * NB)];
            float t1r = c1r + c2r, t1i = c1i + c2i;
            float ur  = c0r - 0.5f * t1r, ui = c0i - 0.5f * t1i;
            const float s3 = 0.8660254037844386f;
            float vr = s3 * (c1r - c2r), vi = s3 * (c1i - c2i);
            float d0r = c0r + t1r, d0i = c0i + t1i;
            float d1r = ur + vi, d1i = ui - vr;        // u - i*v
            float d2r = ur - vi, d2i = ui + vr;        // u + i*v
            float w2r = w1.x * w1.x - w1.y * w1.y;
            float w2i = 2.f * w1.x * w1.y;
            br[S(wb)]         = d0r;
            bi[S(wb)]         = d0i;
            br[S(wb + M)]     = d1r * w1.x - d1i * w1.y;
            bi[S(wb + M)]     = d1r * w1.y + d1i * w1.x;
            br[S(wb + 2 * M)] = d2r * w2r - d2i * w2i;
            bi[S(wb + 2 * M)] = d2r * w2i + d2i * w2r;
        } else {  // R == 2
            float c0r = ar[S(t)],      c0i = ai[S(t)];
            float c1r = ar[S(t + NB)], c1i = ai[S(t + NB)];
            float d1r = c0r - c1r, d1i = c0i - c1i;
            br[S(wb)]     = c0r + c1r;
            bi[S(wb)]     = c0i + c1i;
            br[S(wb + M)] = d1r * w1.x - d1i * w1.y;
            bi[S(wb + M)] = d1r * w1.y + d1i * w1.x;
        }
    }
    __syncthreads();
}

// fft1536 {3,8,8,8}: 4 stages, result lands in x.
__device__ __forceinline__ void fft1536(float* xr, float* xi, float* yr, float* yi,
                                        const float2* tw, int tid) {
    fstage<3, 1,   512>(xr, xi, yr, yi, tw, tid);
    fstage<8, 3,   64 >(yr, yi, xr, xi, tw, tid);
    fstage<8, 24,  8  >(xr, xi, yr, yi, tw, tid);
    fstage<8, 192, 1  >(yr, yi, xr, xi, tw, tid);
}

// fft768 {3,4,8,8}: 4 stages, result lands in x.
__device__ __forceinline__ void fft768(float* xr, float* xi, float* yr, float* yi,
                                       const float2* tw, int tid) {
    fstage<3, 1,   256>(xr, xi, yr, yi, tw, tid);
    fstage<4, 3,   64 >(yr, yi, xr, xi, tw, tid);
    fstage<8, 12,  8  >(xr, xi, yr, yi, tw, tid);
    fstage<8, 96,  1  >(yr, yi, xr, xi, tw, tid);
}

// fft384 {3,2,8,8}: 4 stages, result lands in x.
__device__ __forceinline__ void fft384(float* xr, float* xi, float* yr, float* yi,
                                       const float2* tw, int tid) {
    fstage<3, 1,   128>(xr, xi, yr, yi, tw, tid);
    fstage<2, 3,   64 >(yr, yi, xr, xi, tw, tid);
    fstage<8, 6,   8  >(xr, xi, yr, yi, tw, tid);
    fstage<8, 48,  1  >(yr, yi, xr, xi, tw, tid);
}

// fft192 {3,8,8}: 3 stages, result lands in y.
__device__ __forceinline__ void fft192(float* xr, float* xi, float* yr, float* yi,
                                       const float2* tw, int tid) {
    fstage<3, 1,   64 >(xr, xi, yr, yi, tw, tid);
    fstage<8, 3,   8  >(yr, yi, xr, xi, tw, tid);
    fstage<8, 24,  1  >(xr, xi, yr, yi, tw, tid);
}

// Hermitian split of packed FFT Z = Q + iK; whitened cross-spectrum R into
// (br,bi) for w = 0..N/2 ONLY (inverse uses the half-spectrum form).
__device__ __forceinline__ void herm_split(const float* __restrict__ ar, const float* __restrict__ ai,
                                           float* __restrict__ br, float* __restrict__ bi,
                                           int N, float f, int tid) {
    int half = N >> 1;
    for (int w = tid; w <= half; w += 256) {
        int iw = (w == 0) ? 0 : N - w;
        float Zwr = ar[S(w)],  Zwi = ai[S(w)];
        float Zmr = ar[S(iw)], Zmi = ai[S(iw)];
        float Qx = 0.5f * (Zwr + Zmr), Qy = 0.5f * (Zwi - Zmi);
        float Kx = 0.5f * (Zwi + Zmi), Ky = -0.5f * (Zwr - Zmr);
        float kmag = sqrtf(Kx * Kx + Ky * Ky);
        float sc   = f * f / (f * kmag + 1e-8f);
        br[S(w)] = (Qx * Kx + Qy * Ky) * sc;
        bi[S(w)] = (Qy * Kx - Qx * Ky) * sc;
    }
    __syncthreads();
}

// Build packed half-length inverse input z = E + i*O from half-spectrum R[0..M]
//   E[m] = (R[m] + conj(R[M-m]))/2            (m=0: R[M] unconjugated)
//   O[m] = (R[m] - conj(R[M-m]))/2 * e^{+2*pi*i*m/N},  N = 2M
__device__ __forceinline__ void zbuild(const float* __restrict__ br, const float* __restrict__ bi,
                                       float* __restrict__ zr, float* __restrict__ zi,
                                       int M, int stepN, const float2* __restrict__ tw, int tid) {
    for (int m = tid; m < M; m += 256) {
        int im = M - m;                      // m=0 -> M
        float Rr = br[S(m)],  Ri = bi[S(m)];
        float Cr = br[S(im)], Ci = bi[S(im)];
        if (m) Ci = -Ci;                     // conj for m >= 1
        float Er = 0.5f * (Rr + Cr), Ei = 0.5f * (Ri + Ci);
        float Dr = 0.5f * (Rr - Cr), Di = 0.5f * (Ri - Ci);
        float2 t = tw[m * stepN];
        float wr = t.x, wi = -t.y;           // e^{+2*pi*i*m/N}
        float Or = Dr * wr - Di * wi;
        float Oi = Dr * wi + Di * wr;
        zr[S(m)] = Er - Oi;
        zi[S(m)] = Ei + Or;
    }
    __syncthreads();
}

// c[idx] from forward-FFT'd z (length M): p=idx/2, q=(M-p)%M;
// even idx -> Re zf[q]/M, odd -> Im zf[q]/M (1/M folded into caller's weight).
__device__ __forceinline__ float cval(const float* zr, const float* zi, int M, int idx) {
    int p = idx >> 1;
    int q = p ? (M - p) : 0;
    return (idx & 1) ? zi[S(q)] : zr[S(q)];
}

// ---------------- K2: per-(b,h,e) 3-scale whitened autocorrelation ----------------
__global__ __launch_bounds__(256) void k2_corr() {
    extern __shared__ float sm[];
    float* sq   = sm;             // 1536
    float* sk   = sm + 1536;      // 1536
    float* sacc = sm + 3072;      // 1536
    float* Ar   = sm + 4608;      // 1536
    float* Ai   = sm + 6144;      // 1536
    float* Br   = sm + 7680;      // 1536
    float* Bi   = sm + 9216;      // 1536
    float2* tw  = (float2*)(sm + 10752);  // 768 float2

    int tid = threadIdx.x;
    int bhe = blockIdx.x;
    int b = bhe >> 9;
    const float* qrow = g_qr + (size_t)bhe * LL;
    const float* krow = g_kr + (size_t)bhe * LL;

    const float TWO_PI_OVER = -6.283185307179586f / 1536.f;
    for (int t = tid; t < 768; t += 256) {
        float s, c; __sincosf(TWO_PI_OVER * (float)t, &s, &c);
        tw[t] = make_float2(c, s);
    }
    for (int i = tid; i < LL; i += 256) {
        sq[i] = qrow[i]; sk[i] = krow[i]; sacc[i] = 0.f;
    }
    float f = g_scal[0];
    __syncthreads();

    // ======== scale 1 (N=1536, M=768) ========
    for (int n = tid; n < 1536; n += 256) { Ar[S(n)] = sq[n]; Ai[S(n)] = sk[n]; }
    __syncthreads();
    fft1536(Ar, Ai, Br, Bi, tw, tid);            // Z in A
    herm_split(Ar, Ai, Br, Bi, 1536, f, tid);    // R[0..768] in B
    zbuild(Br, Bi, Ar, Ai, 768, 1, tw, tid);     // z in A
    fft768(Ar, Ai, Br, Bi, tw, tid);             // zf in A
    {
        float wgt = g_scal[1] * (1.f / 768.f);
        for (int l = tid; l < LL; l += 256)
            sacc[l] += wgt * cval(Ar, Ai, 768, l);
    }
    __syncthreads();

    // ======== scale 2 (N=768, M=384) ========
    for (int n = tid; n < 768; n += 256) {
        Ar[S(n)] = 0.5f * (sq[2 * n] + sq[2 * n + 1]);
        Ai[S(n)] = 0.5f * (sk[2 * n] + sk[2 * n + 1]);
    }
    __syncthreads();
    fft768(Ar, Ai, Br, Bi, tw, tid);             // Z in A
    herm_split(Ar, Ai, Br, Bi, 768, f, tid);     // R[0..384] in B
    zbuild(Br, Bi, Ar, Ai, 384, 2, tw, tid);     // z in A
    fft384(Ar, Ai, Br, Bi, tw, tid);             // zf in A
    {
        float wgt = g_scal[2] * (1.f / 384.f);
        const int N = 768;
        for (int l = tid; l < LL; l += 256) {
            float coords = ((float)l + 0.5f) * 0.5f - 0.5f;
            coords = fminf(fmaxf(coords, 0.f), (float)(N - 1));
            int lo = (int)floorf(coords);
            int hi = min(lo + 1, N - 1);
            float fr = coords - (float)lo;
            float clo = cval(Ar, Ai, 384, lo);
            float chi = cval(Ar, Ai, 384, hi);
            sacc[l] += wgt * (clo * (1.f - fr) + chi * fr);
        }
    }
    __syncthreads();

    // ======== scale 4 (N=384, M=192) ========
    for (int n = tid; n < 384; n += 256) {
        Ar[S(n)] = 0.25f * (sq[4 * n] + sq[4 * n + 1] + sq[4 * n + 2] + sq[4 * n + 3]);
        Ai[S(n)] = 0.25f * (sk[4 * n] + sk[4 * n + 1] + sk[4 * n + 2] + sk[4 * n + 3]);
    }
    __syncthreads();
    fft384(Ar, Ai, Br, Bi, tw, tid);             // Z in A
    herm_split(Ar, Ai, Br, Bi, 384, f, tid);     // R[0..192] in B
    zbuild(Br, Bi, Ar, Ai, 192, 4, tw, tid);     // z in A
    fft192(Ar, Ai, Br, Bi, tw, tid);             // zf in B
    {
        float wgt = g_scal[3] * (1.f / 192.f);
        const int N = 384;
        for (int l = tid; l < LL; l += 256) {
            float coords = ((float)l + 0.5f) * 0.25f - 0.5f;
            coords = fminf(fmaxf(coords, 0.f), (float)(N - 1));
            int lo = (int)floorf(coords);
            int hi = min(lo + 1, N - 1);
            float fr = coords - (float)lo;
            float clo = cval(Br, Bi, 192, lo);
            float chi = cval(Br, Bi, 192, hi);
            sacc[l] += wgt * (clo * (1.f - fr) + chi * fr);
        }
    }
    __syncthreads();

    for (int l = tid; l < LL; l += 256) {
        float v = fminf(fmaxf(sacc[l], -10.f), 10.f);
        atomicAdd(&g_mean[b * LL + l], v);
    }
}

// ---------------- K3: per-batch top-7 + softmax (single warp, shuffle-only) ----------------
__global__ __launch_bounds__(32) void k3_topk() {
    int b = blockIdx.x;
    int lane = threadIdx.x;
    float v[48];
    #pragma unroll
    for (int i = 0; i < 48; i++)
        v[i] = g_mean[b * LL + lane + 32 * i] * (1.f / HE);

    float wk[TOPK]; int dk[TOPK];
    for (int it = 0; it < TOPK; it++) {
        float best = -3.0e38f; int bi = 0;
        #pragma unroll
        for (int i = 0; i < 48; i++)
            if (v[i] > best) { best = v[i]; bi = lane + 32 * i; }
        #pragma unroll
        for (int off = 16; off; off >>= 1) {
            float ov = __shfl_down_sync(0xffffffffu, best, off);
            int   oi = __shfl_down_sync(0xffffffffu, bi,   off);
            if (ov > best || (ov == best && oi < bi)) { best = ov; bi = oi; }
        }
        best = __shfl_sync(0xffffffffu, best, 0);
        bi   = __shfl_sync(0xffffffffu, bi,   0);
        wk[it] = best; dk[it] = bi;
        if ((bi & 31) == lane) v[bi >> 5] = -3.0e38f;
    }
    if (lane == 0) {
        float mx = wk[0];
        #pragma unroll
        for (int i = 1; i < TOPK; i++) mx = fmaxf(mx, wk[i]);
        float e[TOPK], ssum = 0.f;
        #pragma unroll
        for (int i = 0; i < TOPK; i++) { e[i] = expf(wk[i] - mx); ssum += e[i]; }
        #pragma unroll
        for (int i = 0; i < TOPK; i++) {
            g_nw[b * TOPK + i] = e[i] / ssum;
            g_delays[b * TOPK + i] = dk[i];
        }
    }
}

// ---------------- K4: delayed-values aggregation ----------------
__global__ __launch_bounds__(128) void k4_out(const float* __restrict__ vals,
                                              float* __restrict__ out) {
    int bl = blockIdx.x;
    int b = bl / LL;
    int l = bl - b * LL;
    int tid = threadIdx.x;
    float nw[TOPK]; int dl[TOPK];
    #pragma unroll
    for (int k = 0; k < TOPK; k++) {
        nw[k] = g_nw[b * TOPK + k];
        dl[k] = g_delays[b * TOPK + k];
    }
    float4 acc = make_float4(0.f, 0.f, 0.f, 0.f);
    #pragma unroll
    for (int k = 0; k < TOPK; k++) {
        int ls = l + dl[k]; if (ls >= LL) ls -= LL;
        const float4* src = (const float4*)(vals + ((size_t)b * LL + ls) * HE);
        float4 v = src[tid];
        acc.x += nw[k] * v.x; acc.y += nw[k] * v.y;
        acc.z += nw[k] * v.z; acc.w += nw[k] * v.w;
    }
    ((float4*)(out + ((size_t)b * LL + l) * HE))[tid] = acc;
}

// ---------------- launch ----------------
extern "C" void kernel_launch(void* const* d_in, const int* in_sizes, int n_in,
                              void* d_out, int out_size) {
    const float* q  = (const float*)d_in[0];
    const float* kk = (const float*)d_in[1];
    const float* v  = (const float*)d_in[2];
    const float* sw = (const float*)d_in[3];
    const float* ff = (const float*)d_in[4];

    const int K2_SMEM = 49152;  // 7*1536*4 + 768*8 = 49152 (== default 48KB cap)

    k0_init<<<48, 256>>>(sw, ff);
    dim3 g1(48, 64, 2);
    k1_ln<<<g1, 256>>>(q, kk);
    k2_corr<<<BHE, 256, K2_SMEM>>>();
    k3_topk<<<BB, 32>>>();
    k4_out<<<BB * LL, 128>>>(v, (float*)d_out);
}

// round 6
// speedup vs baseline: 1.0165x; 1.0165x over previous
#include <cuda_runtime.h>
#include <math.h>

#define BB 8
#define LL 1536
#define HH 8
#define EE 64
#define HE 512          // H*E
#define BHE 4096        // B*H*E
#define TOPK 7          // int(log(1536)) = 7

// ---------------- scratch (static __device__, no allocation) ----------------
__device__ float g_qr[(size_t)BHE * LL];   // layernormed q, (b,h,e,l)
__device__ float g_kr[(size_t)BHE * LL];   // layernormed k, (b,h,e,l)
__device__ float g_mean[BB * LL];          // sum over (h,e) of clipped corr
__device__ float g_scal[4];                // [0]=sigmoid(freq), [1..3]=softmax(scale_weights)
__device__ int   g_delays[BB * TOPK];
__device__ float g_nw[BB * TOPK];

// ---------------- K0: scalars + zero mean accumulator ----------------
__global__ void k0_init(const float* __restrict__ sw, const float* __restrict__ ff) {
    int idx = blockIdx.x * blockDim.x + threadIdx.x;
    for (int i = idx; i < BB * LL; i += gridDim.x * blockDim.x) g_mean[i] = 0.f;
    if (idx == 0) {
        g_scal[0] = 1.f / (1.f + expf(-ff[0]));
        float a = sw[0], b = sw[1], c = sw[2];
        float mx = fmaxf(a, fmaxf(b, c));
        float ea = expf(a - mx), eb = expf(b - mx), ec = expf(c - mx);
        float s = ea + eb + ec;
        g_scal[1] = ea / s; g_scal[2] = eb / s; g_scal[3] = ec / s;
    }
}

// ---------------- K1: LayerNorm over E + transpose to (b,h,e,l) ----------------
__global__ __launch_bounds__(256) void k1_ln(const float* __restrict__ q,
                                             const float* __restrict__ kk) {
    __shared__ float tile[32][EE + 1];
    __shared__ float mu[32], isd[32];
    int l0 = blockIdx.x * 32;
    int bh = blockIdx.y;                 // b*8 + h
    int b  = bh >> 3, h = bh & 7;
    const float* in = blockIdx.z ? kk : q;
    float* out      = blockIdx.z ? g_kr : g_qr;
    int tid = threadIdx.x;
    int e = tid & 63, r0 = tid >> 6;
    for (int r = r0; r < 32; r += 4)
        tile[r][e] = in[(((size_t)b * LL + l0 + r) * HH + h) * EE + e];
    __syncthreads();
    int lane = tid & 31, w = tid >> 5;
    for (int r = w; r < 32; r += 8) {
        float x0 = tile[r][lane], x1 = tile[r][lane + 32];
        float s = x0 + x1, s2 = x0 * x0 + x1 * x1;
        #pragma unroll
        for (int off = 16; off; off >>= 1) {
            s  += __shfl_down_sync(0xffffffffu, s,  off);
            s2 += __shfl_down_sync(0xffffffffu, s2, off);
        }
        if (lane == 0) {
            float m = s * (1.f / EE);
            float v = s2 * (1.f / EE) - m * m;
            mu[r] = m; isd[r] = rsqrtf(v + 1e-5f);
        }
    }
    __syncthreads();
    int li = tid & 31, e0 = tid >> 5;
    for (int ee = e0; ee < EE; ee += 8) {
        float val = (tile[li][ee] - mu[li]) * isd[li];
        out[(((size_t)bh) * EE + ee) * LL + l0 + li] = val;
    }
}

// ---------------- FFT: templated Stockham, SoA + XOR bank swizzle, radix-4 ----
// tw[t] = exp(-2*pi*i*t/1536), t in [0,768). Stage twiddle = tw[j * (1536/(R*L))].
// All FFT buffer indices pass through S(): bijection within each 32-word block.

__device__ __forceinline__ int S(int a) { return a ^ ((a >> 5) & 31); }

template<int R, int M, int L>
__device__ __forceinline__ void fstage(const float* __restrict__ ar, const float* __restrict__ ai,
                                       float* __restrict__ br, float* __restrict__ bi,
                                       const float2* __restrict__ tw, int tid) {
    constexpr int NB   = L * M;            // butterflies; also the input stride
    constexpr int STEP = 1536 / (R * L);
    for (int t = tid; t < NB; t += 256) {
        int j = t / M;                     // compile-time M -> mul/shift
        int k = t - j * M;
        int wb = k + (M * R) * j;
        float2 w1 = tw[j * STEP];
        if (R == 4) {
            float c0r = ar[S(t)],          c0i = ai[S(t)];
            float c1r = ar[S(t + NB)],     c1i = ai[S(t + NB)];
            float c2r = ar[S(t + 2 * NB)], c2i = ai[S(t + 2 * NB)];
            float c3r = ar[S(t + 3 * NB)], c3i = ai[S(t + 3 * NB)];
            float t0r = c0r + c2r, t0i = c0i + c2i;
            float t1r = c0r - c2r, t1i = c0i - c2i;
            float t2r = c1r + c3r, t2i = c1i + c3i;
            float t3r = c1r - c3r, t3i = c1i - c3i;
            float d0r = t0r + t2r, d0i = t0i + t2i;
            float d2r = t0r - t2r, d2i = t0i - t2i;
            float d1r = t1r + t3i, d1i = t1i - t3r;   // t1 - i*t3
            float d3r = t1r - t3i, d3i = t1i + t3r;   // t1 + i*t3
            float w2r = w1.x * w1.x - w1.y * w1.y;
            float w2i = 2.f * w1.x * w1.y;
            float w3r = w2r * w1.x - w2i * w1.y;
            float w3i = w2r * w1.y + w2i * w1.x;
            br[S(wb)]         = d0r;
            bi[S(wb)]         = d0i;
            br[S(wb + M)]     = d1r * w1.x - d1i * w1.y;
            bi[S(wb + M)]     = d1r * w1.y + d1i * w1.x;
            br[S(wb + 2 * M)] = d2r * w2r - d2i * w2i;
            bi[S(wb + 2 * M)] = d2r * w2i + d2i * w2r;
            br[S(wb + 3 * M)] = d3r * w3r - d3i * w3i;
            bi[S(wb + 3 * M)] = d3r * w3i + d3i * w3r;
        } else if (R == 3) {
            float c0r = ar[S(t)],          c0i = ai[S(t)];
            float c1r = ar[S(t + NB)],     c1i = ai[S(t + NB)];
            float c2r = ar[S(t + 2 * NB)], c2i = ai[S(t + 2 * NB)];
            float t1r = c1r + c2r, t1i = c1i + c2i;
            float ur  = c0r - 0.5f * t1r, ui = c0i - 0.5f * t1i;
            const float s3 = 0.8660254037844386f;
            float vr = s3 * (c1r - c2r), vi = s3 * (c1i - c2i);
            float d0r = c0r + t1r, d0i = c0i + t1i;
            float d1r = ur + vi, d1i = ui - vr;        // u - i*v
            float d2r = ur - vi, d2i = ui + vr;        // u + i*v
            float w2r = w1.x * w1.x - w1.y * w1.y;
            float w2i = 2.f * w1.x * w1.y;
            br[S(wb)]         = d0r;
            bi[S(wb)]         = d0i;
            br[S(wb + M)]     = d1r * w1.x - d1i * w1.y;
            bi[S(wb + M)]     = d1r * w1.y + d1i * w1.x;
            br[S(wb + 2 * M)] = d2r * w2r - d2i * w2i;
            bi[S(wb + 2 * M)] = d2r * w2i + d2i * w2r;
        } else {  // R == 2
            float c0r = ar[S(t)],      c0i = ai[S(t)];
            float c1r = ar[S(t + NB)], c1i = ai[S(t + NB)];
            float d1r = c0r - c1r, d1i = c0i - c1i;
            br[S(wb)]     = c0r + c1r;
            bi[S(wb)]     = c0i + c1i;
            br[S(wb + M)] = d1r * w1.x - d1i * w1.y;
            bi[S(wb + M)] = d1r * w1.y + d1i * w1.x;
        }
    }
    __syncthreads();
}

// fft1536 reading stage 1 from zc (zc preserved); 6 stages, result in y.
__device__ __forceinline__ void fft1536_from(const float* zcr, const float* zci,
                                             float* xr, float* xi, float* yr, float* yi,
                                             const float2* tw, int tid) {
    fstage<3, 1,   512>(zcr, zci, xr, xi, tw, tid);
    fstage<4, 3,   128>(xr, xi, yr, yi, tw, tid);
    fstage<4, 12,  32 >(yr, yi, xr, xi, tw, tid);
    fstage<4, 48,  8  >(xr, xi, yr, yi, tw, tid);
    fstage<4, 192, 2  >(yr, yi, xr, xi, tw, tid);
    fstage<2, 768, 1  >(xr, xi, yr, yi, tw, tid);
}

// fft768(x,y): 5 stages, result in y.
__device__ __forceinline__ void fft768(float* xr, float* xi, float* yr, float* yi,
                                       const float2* tw, int tid) {
    fstage<3, 1,   256>(xr, xi, yr, yi, tw, tid);
    fstage<4, 3,   64 >(yr, yi, xr, xi, tw, tid);
    fstage<4, 12,  16 >(xr, xi, yr, yi, tw, tid);
    fstage<4, 48,  4  >(yr, yi, xr, xi, tw, tid);
    fstage<4, 192, 1  >(xr, xi, yr, yi, tw, tid);
}

// fft384(x,y): 5 stages, result in y.
__device__ __forceinline__ void fft384(float* xr, float* xi, float* yr, float* yi,
                                       const float2* tw, int tid) {
    fstage<3, 1,   128>(xr, xi, yr, yi, tw, tid);
    fstage<4, 3,   32 >(yr, yi, xr, xi, tw, tid);
    fstage<4, 12,  8  >(xr, xi, yr, yi, tw, tid);
    fstage<4, 48,  2  >(yr, yi, xr, xi, tw, tid);
    fstage<2, 192, 1  >(xr, xi, yr, yi, tw, tid);
}

// fft192(x,y): 4 stages, result in x.
__device__ __forceinline__ void fft192(float* xr, float* xi, float* yr, float* yi,
                                       const float2* tw, int tid) {
    fstage<3, 1,   64 >(xr, xi, yr, yi, tw, tid);
    fstage<4, 3,   16 >(yr, yi, xr, xi, tw, tid);
    fstage<4, 12,  4  >(xr, xi, yr, yi, tw, tid);
    fstage<4, 48,  1  >(yr, yi, xr, xi, tw, tid);
}

// Hermitian split of packed FFT Z = Q + iK; whitened cross-spectrum R into
// (br,bi) for w = 0..N/2 ONLY (inverse uses the half-spectrum form).
__device__ __forceinline__ void herm_split(const float* __restrict__ ar, const float* __restrict__ ai,
                                           float* __restrict__ br, float* __restrict__ bi,
                                           int N, float f, int tid) {
    int half = N >> 1;
    for (int w = tid; w <= half; w += 256) {
        int iw = (w == 0) ? 0 : N - w;
        float Zwr = ar[S(w)],  Zwi = ai[S(w)];
        float Zmr = ar[S(iw)], Zmi = ai[S(iw)];
        float Qx = 0.5f * (Zwr + Zmr), Qy = 0.5f * (Zwi - Zmi);
        float Kx = 0.5f * (Zwi + Zmi), Ky = -0.5f * (Zwr - Zmr);
        float kmag = sqrtf(Kx * Kx + Ky * Ky);
        float sc   = f * f / (f * kmag + 1e-8f);
        br[S(w)] = (Qx * Kx + Qy * Ky) * sc;
        bi[S(w)] = (Qy * Kx - Qx * Ky) * sc;
    }
    __syncthreads();
}

// Build packed half-length inverse input z = E + i*O from half-spectrum R[0..M]
//   E[m] = (R[m] + conj(R[M-m]))/2            (m=0: R[M] unconjugated)
//   O[m] = (R[m] - conj(R[M-m]))/2 * e^{+2*pi*i*m/N},  N = 2M
__device__ __forceinline__ void zbuild(const float* __restrict__ br, const float* __restrict__ bi,
                                       float* __restrict__ zr, float* __restrict__ zi,
                                       int M, int stepN, const float2* __restrict__ tw, int tid) {
    for (int m = tid; m < M; m += 256) {
        int im = M - m;                      // m=0 -> M
        float Rr = br[S(m)],  Ri = bi[S(m)];
        float Cr = br[S(im)], Ci = bi[S(im)];
        if (m) Ci = -Ci;                     // conj for m >= 1
        float Er = 0.5f * (Rr + Cr), Ei = 0.5f * (Ri + Ci);
        float Dr = 0.5f * (Rr - Cr), Di = 0.5f * (Ri - Ci);
        float2 t = tw[m * stepN];
        float wr = t.x, wi = -t.y;           // e^{+2*pi*i*m/N}
        float Or = Dr * wr - Di * wi;
        float Oi = Dr * wi + Di * wr;
        zr[S(m)] = Er - Oi;
        zi[S(m)] = Ei + Or;
    }
    __syncthreads();
}

// c[idx] from forward-FFT'd z (length M): p=idx/2, q=(M-p)%M;
// even idx -> Re zf[q]/M, odd -> Im zf[q]/M (1/M folded into caller's weight).
__device__ __forceinline__ float cval(const float* zr, const float* zi, int M, int idx) {
    int p = idx >> 1;
    int q = p ? (M - p) : 0;
    return (idx & 1) ? zi[S(q)] : zr[S(q)];
}

// ---------------- K2: per-(b,h,e) 3-scale whitened autocorrelation ----------------
// smem: zc (preserved packed input) + A + B work buffers + twiddle LUT = 43008 B
// -> 5 CTAs/SM. Per-l accumulator lives in registers (6 per thread).
__global__ __launch_bounds__(256) void k2_corr() {
    extern __shared__ float sm[];
    float* zcr  = sm;             // 1536
    float* zci  = sm + 1536;      // 1536
    float* Ar   = sm + 3072;      // 1536
    float* Ai   = sm + 4608;      // 1536
    float* Br   = sm + 6144;      // 1536
    float* Bi   = sm + 7680;      // 1536
    float2* tw  = (float2*)(sm + 9216);   // 768 float2 (6144 B)

    int tid = threadIdx.x;
    int bhe = blockIdx.x;
    int b = bhe >> 9;
    const float* qrow = g_qr + (size_t)bhe * LL;
    const float* krow = g_kr + (size_t)bhe * LL;

    const float TWO_PI_OVER = -6.283185307179586f / 1536.f;
    for (int t = tid; t < 768; t += 256) {
        float s, c; __sincosf(TWO_PI_OVER * (float)t, &s, &c);
        tw[t] = make_float2(c, s);
    }
    for (int i = tid; i < LL; i += 256) {
        zcr[S(i)] = qrow[i];
        zci[S(i)] = krow[i];
    }
    float f = g_scal[0];
    float acc0 = 0.f, acc1 = 0.f, acc2 = 0.f, acc3 = 0.f, acc4 = 0.f, acc5 = 0.f;
    __syncthreads();

    // ======== scale 1 (N=1536, M=768) ========
    fft1536_from(zcr, zci, Ar, Ai, Br, Bi, tw, tid);  // Z in B, zc preserved
    herm_split(Br, Bi, Ar, Ai, 1536, f, tid);         // R[0..768] in A
    zbuild(Ar, Ai, Br, Bi, 768, 1, tw, tid);          // z in B
    fft768(Br, Bi, Ar, Ai, tw, tid);                  // zf in A
    {
        float wgt = g_scal[1] * (1.f / 768.f);
        acc0 += wgt * cval(Ar, Ai, 768, tid);
        acc1 += wgt * cval(Ar, Ai, 768, tid + 256);
        acc2 += wgt * cval(Ar, Ai, 768, tid + 512);
        acc3 += wgt * cval(Ar, Ai, 768, tid + 768);
        acc4 += wgt * cval(Ar, Ai, 768, tid + 1024);
        acc5 += wgt * cval(Ar, Ai, 768, tid + 1280);
    }
    __syncthreads();

    // ======== scale 2 (N=768, M=384) ========
    for (int n = tid; n < 768; n += 256) {
        Ar[S(n)] = 0.5f * (zcr[S(2 * n)] + zcr[S(2 * n + 1)]);
        Ai[S(n)] = 0.5f * (zci[S(2 * n)] + zci[S(2 * n + 1)]);
    }
    __syncthreads();
    fft768(Ar, Ai, Br, Bi, tw, tid);                  // Z in B
    herm_split(Br, Bi, Ar, Ai, 768, f, tid);          // R[0..384] in A
    zbuild(Ar, Ai, Br, Bi, 384, 2, tw, tid);          // z in B
    fft384(Br, Bi, Ar, Ai, tw, tid);                  // zf in A
    {
        float wgt = g_scal[2] * (1.f / 384.f);
        const int N = 768;
        #pragma unroll
        for (int i = 0; i < 6; i++) {
            int l = tid + 256 * i;
            float coords = ((float)l + 0.5f) * 0.5f - 0.5f;
            coords = fminf(fmaxf(coords, 0.f), (float)(N - 1));
            int lo = (int)floorf(coords);
            int hi = min(lo + 1, N - 1);
            float fr = coords - (float)lo;
            float clo = cval(Ar, Ai, 384, lo);
            float chi = cval(Ar, Ai, 384, hi);
            float add = wgt * (clo * (1.f - fr) + chi * fr);
            if (i == 0) acc0 += add; else if (i == 1) acc1 += add;
            else if (i == 2) acc2 += add; else if (i == 3) acc3 += add;
            else if (i == 4) acc4 += add; else acc5 += add;
        }
    }
    __syncthreads();

    // ======== scale 4 (N=384, M=192) ========
    for (int n = tid; n < 384; n += 256) {
        Ar[S(n)] = 0.25f * (zcr[S(4 * n)] + zcr[S(4 * n + 1)] + zcr[S(4 * n + 2)] + zcr[S(4 * n + 3)]);
        Ai[S(n)] = 0.25f * (zci[S(4 * n)] + zci[S(4 * n + 1)] + zci[S(4 * n + 2)] + zci[S(4 * n + 3)]);
    }
    __syncthreads();
    fft384(Ar, Ai, Br, Bi, tw, tid);                  // Z in B
    herm_split(Br, Bi, Ar, Ai, 384, f, tid);          // R[0..192] in A
    zbuild(Ar, Ai, Br, Bi, 192, 4, tw, tid);          // z in B
    fft192(Br, Bi, Ar, Ai, tw, tid);                  // zf in B
    {
        float wgt = g_scal[3] * (1.f / 192.f);
        const int N = 384;
        #pragma unroll
        for (int i = 0; i < 6; i++) {
            int l = tid + 256 * i;
            float coords = ((float)l + 0.5f) * 0.25f - 0.5f;
            coords = fminf(fmaxf(coords, 0.f), (float)(N - 1));
            int lo = (int)floorf(coords);
            int hi = min(lo + 1, N - 1);
            float fr = coords - (float)lo;
            float clo = cval(Br, Bi, 192, lo);
            float chi = cval(Br, Bi, 192, hi);
            float add = wgt * (clo * (1.f - fr) + chi * fr);
            if (i == 0) acc0 += add; else if (i == 1) acc1 += add;
            else if (i == 2) acc2 += add; else if (i == 3) acc3 += add;
            else if (i == 4) acc4 += add; else acc5 += add;
        }
    }

    float* gm = g_mean + b * LL;
    atomicAdd(gm + tid,        fminf(fmaxf(acc0, -10.f), 10.f));
    atomicAdd(gm + tid + 256,  fminf(fmaxf(acc1, -10.f), 10.f));
    atomicAdd(gm + tid + 512,  fminf(fmaxf(acc2, -10.f), 10.f));
    atomicAdd(gm + tid + 768,  fminf(fmaxf(acc3, -10.f), 10.f));
    atomicAdd(gm + tid + 1024, fminf(fmaxf(acc4, -10.f), 10.f));
    atomicAdd(gm + tid + 1280, fminf(fmaxf(acc5, -10.f), 10.f));
}

// ---------------- K3: per-batch top-7 + softmax (single warp, shuffle-only) ----------------
__global__ __launch_bounds__(32) void k3_topk() {
    int b = blockIdx.x;
    int lane = threadIdx.x;
    float v[48];
    #pragma unroll
    for (int i = 0; i < 48; i++)
        v[i] = g_mean[b * LL + lane + 32 * i] * (1.f / HE);

    float wk[TOPK]; int dk[TOPK];
    for (int it = 0; it < TOPK; it++) {
        float best = -3.0e38f; int bi = 0;
        #pragma unroll
        for (int i = 0; i < 48; i++)
            if (v[i] > best) { best = v[i]; bi = lane + 32 * i; }
        #pragma unroll
        for (int off = 16; off; off >>= 1) {
            float ov = __shfl_down_sync(0xffffffffu, best, off);
            int   oi = __shfl_down_sync(0xffffffffu, bi,   off);
            if (ov > best || (ov == best && oi < bi)) { best = ov; bi = oi; }
        }
        best = __shfl_sync(0xffffffffu, best, 0);
        bi   = __shfl_sync(0xffffffffu, bi,   0);
        wk[it] = best; dk[it] = bi;
        if ((bi & 31) == lane) v[bi >> 5] = -3.0e38f;
    }
    if (lane == 0) {
        float mx = wk[0];
        #pragma unroll
        for (int i = 1; i < TOPK; i++) mx = fmaxf(mx, wk[i]);
        float e[TOPK], ssum = 0.f;
        #pragma unroll
        for (int i = 0; i < TOPK; i++) { e[i] = expf(wk[i] - mx); ssum += e[i]; }
        #pragma unroll
        for (int i = 0; i < TOPK; i++) {
            g_nw[b * TOPK + i] = e[i] / ssum;
            g_delays[b * TOPK + i] = dk[i];
        }
    }
}

// ---------------- K4: delayed-values aggregation ----------------
__global__ __launch_bounds__(128) void k4_out(const float* __restrict__ vals,
                                              float* __restrict__ out) {
    int bl = blockIdx.x;
    int b = bl / LL;
    int l = bl - b * LL;
    int tid = threadIdx.x;
    float nw[TOPK]; int dl[TOPK];
    #pragma unroll
    for (int k = 0; k < TOPK; k++) {
        nw[k] = g_nw[b * TOPK + k];
        dl[k] = g_delays[b * TOPK + k];
    }
    float4 acc = make_float4(0.f, 0.f, 0.f, 0.f);
    #pragma unroll
    for (int k = 0; k < TOPK; k++) {
        int ls = l + dl[k]; if (ls >= LL) ls -= LL;
        const float4* src = (const float4*)(vals + ((size_t)b * LL + ls) * HE);
        float4 v = src[tid];
        acc.x += nw[k] * v.x; acc.y += nw[k] * v.y;
        acc.z += nw[k] * v.z; acc.w += nw[k] * v.w;
    }
    ((float4*)(out + ((size_t)b * LL + l) * HE))[tid] = acc;
}

// ---------------- launch ----------------
extern "C" void kernel_launch(void* const* d_in, const int* in_sizes, int n_in,
                              void* d_out, int out_size) {
    const float* q  = (const float*)d_in[0];
    const float* kk = (const float*)d_in[1];
    const float* v  = (const float*)d_in[2];
    const float* sw = (const float*)d_in[3];
    const float* ff = (const float*)d_in[4];

    const int K2_SMEM = 43008;  // 6*1536*4 + 768*8 = 36864 + 6144

    k0_init<<<48, 256>>>(sw, ff);
    dim3 g1(48, 64, 2);
    k1_ln<<<g1, 256>>>(q, kk);
    k2_corr<<<BHE, 256, K2_SMEM>>>();
    k3_topk<<<BB, 32>>>();
    k4_out<<<BB * LL, 128>>>(v, (float*)d_out);
}

// round 7
// speedup vs baseline: 1.1952x; 1.1757x over previous
#include <cuda_runtime.h>
#include <math.h>

#define BB 8
#define LL 1536
#define HH 8
#define EE 64
#define HE 512          // H*E
#define BHE 4096        // B*H*E
#define TOPK 7          // int(log(1536)) = 7

// ---------------- scratch (static __device__, no allocation) ----------------
__device__ float g_qr[(size_t)BHE * LL];   // layernormed q, (b,h,e,l)
__device__ float g_kr[(size_t)BHE * LL];   // layernormed k, (b,h,e,l)
__device__ float g_mean[BB * LL];          // sum over (h,e) of clipped corr
__device__ float g_scal[4];                // [0]=sigmoid(freq), [1..3]=softmax(scale_weights)
__device__ int   g_delays[BB * TOPK];
__device__ float g_nw[BB * TOPK];

// ---------------- K0: scalars + zero mean accumulator ----------------
__global__ void k0_init(const float* __restrict__ sw, const float* __restrict__ ff) {
    int idx = blockIdx.x * blockDim.x + threadIdx.x;
    for (int i = idx; i < BB * LL; i += gridDim.x * blockDim.x) g_mean[i] = 0.f;
    if (idx == 0) {
        g_scal[0] = 1.f / (1.f + expf(-ff[0]));
        float a = sw[0], b = sw[1], c = sw[2];
        float mx = fmaxf(a, fmaxf(b, c));
        float ea = expf(a - mx), eb = expf(b - mx), ec = expf(c - mx);
        float s = ea + eb + ec;
        g_scal[1] = ea / s; g_scal[2] = eb / s; g_scal[3] = ec / s;
    }
}

// ---------------- K1: LayerNorm over E + transpose to (b,h,e,l) ----------------
__global__ __launch_bounds__(256) void k1_ln(const float* __restrict__ q,
                                             const float* __restrict__ kk) {
    __shared__ float tile[32][EE + 1];
    __shared__ float mu[32], isd[32];
    int l0 = blockIdx.x * 32;
    int bh = blockIdx.y;                 // b*8 + h
    int b  = bh >> 3, h = bh & 7;
    const float* in = blockIdx.z ? kk : q;
    float* out      = blockIdx.z ? g_kr : g_qr;
    int tid = threadIdx.x;
    int e = tid & 63, r0 = tid >> 6;
    for (int r = r0; r < 32; r += 4)
        tile[r][e] = in[(((size_t)b * LL + l0 + r) * HH + h) * EE + e];
    __syncthreads();
    int lane = tid & 31, w = tid >> 5;
    for (int r = w; r < 32; r += 8) {
        float x0 = tile[r][lane], x1 = tile[r][lane + 32];
        float s = x0 + x1, s2 = x0 * x0 + x1 * x1;
        #pragma unroll
        for (int off = 16; off; off >>= 1) {
            s  += __shfl_down_sync(0xffffffffu, s,  off);
            s2 += __shfl_down_sync(0xffffffffu, s2, off);
        }
        if (lane == 0) {
            float m = s * (1.f / EE);
            float v = s2 * (1.f / EE) - m * m;
            mu[r] = m; isd[r] = rsqrtf(v + 1e-5f);
        }
    }
    __syncthreads();
    int li = tid & 31, e0 = tid >> 5;
    for (int ee = e0; ee < EE; ee += 8) {
        float val = (tile[li][ee] - mu[li]) * isd[li];
        out[(((size_t)bh) * EE + ee) * LL + l0 + li] = val;
    }
}

// ---------------- FFT: templated Stockham stages, SoA, twiddle LUT ----------------
// tw[t] = exp(-2*pi*i*t/1536), t in [0,768). Stage twiddle = tw[j * (1536/(R*L))].

template<int R, int M, int L>
__device__ __forceinline__ void fstage(const float* __restrict__ ar, const float* __restrict__ ai,
                                       float* __restrict__ br, float* __restrict__ bi,
                                       const float2* __restrict__ tw, int tid) {
    constexpr int NB   = L * M;            // butterflies; also the input stride
    constexpr int STEP = 1536 / (R * L);
    for (int t = tid; t < NB; t += 256) {
        int j = t / M;                     // compile-time M -> mul/shift
        int k = t - j * M;
        int wb = k + (M * R) * j;
        float2 w1 = tw[j * STEP];
        if (R == 4) {
            float c0r = ar[t],          c0i = ai[t];
            float c1r = ar[t + NB],     c1i = ai[t + NB];
            float c2r = ar[t + 2 * NB], c2i = ai[t + 2 * NB];
            float c3r = ar[t + 3 * NB], c3i = ai[t + 3 * NB];
            float t0r = c0r + c2r, t0i = c0i + c2i;
            float t1r = c0r - c2r, t1i = c0i - c2i;
            float t2r = c1r + c3r, t2i = c1i + c3i;
            float t3r = c1r - c3r, t3i = c1i - c3i;
            float d0r = t0r + t2r, d0i = t0i + t2i;
            float d2r = t0r - t2r, d2i = t0i - t2i;
            float d1r = t1r + t3i, d1i = t1i - t3r;   // t1 - i*t3
            float d3r = t1r - t3i, d3i = t1i + t3r;   // t1 + i*t3
            float w2r = w1.x * w1.x - w1.y * w1.y;
            float w2i = 2.f * w1.x * w1.y;
            float w3r = w2r * w1.x - w2i * w1.y;
            float w3i = w2r * w1.y + w2i * w1.x;
            br[wb]         = d0r;
            bi[wb]         = d0i;
            br[wb + M]     = d1r * w1.x - d1i * w1.y;
            bi[wb + M]     = d1r * w1.y + d1i * w1.x;
            br[wb + 2 * M] = d2r * w2r - d2i * w2i;
            bi[wb + 2 * M] = d2r * w2i + d2i * w2r;
            br[wb + 3 * M] = d3r * w3r - d3i * w3i;
            bi[wb + 3 * M] = d3r * w3i + d3i * w3r;
        } else if (R == 3) {
            float c0r = ar[t],          c0i = ai[t];
            float c1r = ar[t + NB],     c1i = ai[t + NB];
            float c2r = ar[t + 2 * NB], c2i = ai[t + 2 * NB];
            float t1r = c1r + c2r, t1i = c1i + c2i;
            float ur  = c0r - 0.5f * t1r, ui = c0i - 0.5f * t1i;
            const float s3 = 0.8660254037844386f;
            float vr = s3 * (c1r - c2r), vi = s3 * (c1i - c2i);
            float d0r = c0r + t1r, d0i = c0i + t1i;
            float d1r = ur + vi, d1i = ui - vr;        // u - i*v
            float d2r = ur - vi, d2i = ui + vr;        // u + i*v
            float w2r = w1.x * w1.x - w1.y * w1.y;
            float w2i = 2.f * w1.x * w1.y;
            br[wb]         = d0r;
            bi[wb]         = d0i;
            br[wb + M]     = d1r * w1.x - d1i * w1.y;
            bi[wb + M]     = d1r * w1.y + d1i * w1.x;
            br[wb + 2 * M] = d2r * w2r - d2i * w2i;
            bi[wb + 2 * M] = d2r * w2i + d2i * w2r;
        } else {  // R == 2
            float c0r = ar[t],      c0i = ai[t];
            float c1r = ar[t + NB], c1i = ai[t + NB];
            float d1r = c0r - c1r, d1i = c0i - c1i;
            br[wb]     = c0r + c1r;
            bi[wb]     = c0i + c1i;
            br[wb + M] = d1r * w1.x - d1i * w1.y;
            bi[wb + M] = d1r * w1.y + d1i * w1.x;
        }
    }
    __syncthreads();
}

// fft1536 reading stage 1 from zc (zc preserved); 6 stages, result in y.
__device__ __forceinline__ void fft1536_from(const float* zcr, const float* zci,
                                             float* xr, float* xi, float* yr, float* yi,
                                             const float2* tw, int tid) {
    fstage<3, 1,   512>(zcr, zci, xr, xi, tw, tid);
    fstage<4, 3,   128>(xr, xi, yr, yi, tw, tid);
    fstage<4, 12,  32 >(yr, yi, xr, xi, tw, tid);
    fstage<4, 48,  8  >(xr, xi, yr, yi, tw, tid);
    fstage<4, 192, 2  >(yr, yi, xr, xi, tw, tid);
    fstage<2, 768, 1  >(xr, xi, yr, yi, tw, tid);
}

// fft768(x,y): 5 stages, result in y.
__device__ __forceinline__ void fft768(float* xr, float* xi, float* yr, float* yi,
                                       const float2* tw, int tid) {
    fstage<3, 1,   256>(xr, xi, yr, yi, tw, tid);
    fstage<4, 3,   64 >(yr, yi, xr, xi, tw, tid);
    fstage<4, 12,  16 >(xr, xi, yr, yi, tw, tid);
    fstage<4, 48,  4  >(yr, yi, xr, xi, tw, tid);
    fstage<4, 192, 1  >(xr, xi, yr, yi, tw, tid);
}

// fft384(x,y): 5 stages, result in y.
__device__ __forceinline__ void fft384(float* xr, float* xi, float* yr, float* yi,
                                       const float2* tw, int tid) {
    fstage<3, 1,   128>(xr, xi, yr, yi, tw, tid);
    fstage<4, 3,   32 >(yr, yi, xr, xi, tw, tid);
    fstage<4, 12,  8  >(xr, xi, yr, yi, tw, tid);
    fstage<4, 48,  2  >(yr, yi, xr, xi, tw, tid);
    fstage<2, 192, 1  >(xr, xi, yr, yi, tw, tid);
}

// fft192(x,y): 4 stages, result in x.
__device__ __forceinline__ void fft192(float* xr, float* xi, float* yr, float* yi,
                                       const float2* tw, int tid) {
    fstage<3, 1,   64 >(xr, xi, yr, yi, tw, tid);
    fstage<4, 3,   16 >(yr, yi, xr, xi, tw, tid);
    fstage<4, 12,  4  >(xr, xi, yr, yi, tw, tid);
    fstage<4, 48,  1  >(yr, yi, xr, xi, tw, tid);
}

// Hermitian split of packed FFT Z = Q + iK; whitened cross-spectrum R into
// (br,bi) for w = 0..N/2 ONLY (inverse uses the half-spectrum form).
__device__ __forceinline__ void herm_split(const float* __restrict__ ar, const float* __restrict__ ai,
                                           float* __restrict__ br, float* __restrict__ bi,
                                           int N, float f, int tid) {
    int half = N >> 1;
    for (int w = tid; w <= half; w += 256) {
        int iw = (w == 0) ? 0 : N - w;
        float Zwr = ar[w],  Zwi = ai[w];
        float Zmr = ar[iw], Zmi = ai[iw];
        float Qx = 0.5f * (Zwr + Zmr), Qy = 0.5f * (Zwi - Zmi);
        float Kx = 0.5f * (Zwi + Zmi), Ky = -0.5f * (Zwr - Zmr);
        float kmag = sqrtf(Kx * Kx + Ky * Ky);
        float sc   = f * f / (f * kmag + 1e-8f);
        br[w] = (Qx * Kx + Qy * Ky) * sc;
        bi[w] = (Qy * Kx - Qx * Ky) * sc;
    }
    __syncthreads();
}

// Build packed half-length inverse input z = E + i*O from half-spectrum R[0..M]
//   E[m] = (R[m] + conj(R[M-m]))/2            (m=0: R[M] unconjugated)
//   O[m] = (R[m] - conj(R[M-m]))/2 * e^{+2*pi*i*m/N},  N = 2M
__device__ __forceinline__ void zbuild(const float* __restrict__ br, const float* __restrict__ bi,
                                       float* __restrict__ zr, float* __restrict__ zi,
                                       int M, int stepN, const float2* __restrict__ tw, int tid) {
    for (int m = tid; m < M; m += 256) {
        int im = M - m;                      // m=0 -> M
        float Rr = br[m],  Ri = bi[m];
        float Cr = br[im], Ci = bi[im];
        if (m) Ci = -Ci;                     // conj for m >= 1
        float Er = 0.5f * (Rr + Cr), Ei = 0.5f * (Ri + Ci);
        float Dr = 0.5f * (Rr - Cr), Di = 0.5f * (Ri - Ci);
        float2 t = tw[m * stepN];
        float wr = t.x, wi = -t.y;           // e^{+2*pi*i*m/N}
        float Or = Dr * wr - Di * wi;
        float Oi = Dr * wi + Di * wr;
        zr[m] = Er - Oi;
        zi[m] = Ei + Or;
    }
    __syncthreads();
}

// c[idx] from forward-FFT'd z (length M): p=idx/2, q=(M-p)%M;
// even idx -> Re zf[q]/M, odd -> Im zf[q]/M (1/M folded into caller's weight).
__device__ __forceinline__ float cval(const float* zr, const float* zi, int M, int idx) {
    int p = idx >> 1;
    int q = p ? (M - p) : 0;
    return (idx & 1) ? zi[q] : zr[q];
}

// ---------------- K2: per-(b,h,e) 3-scale whitened autocorrelation ----------------
// smem: zc (preserved packed input) + A + B work buffers + twiddle LUT = 43008 B
// -> 5 CTAs/SM. Per-l accumulator lives in registers (6 per thread). No swizzle
// (R5/R6 showed swizzle arithmetic costs more than the ~2-way conflicts it removes).
__global__ __launch_bounds__(256) void k2_corr() {
    extern __shared__ float sm[];
    float* zcr  = sm;             // 1536
    float* zci  = sm + 1536;      // 1536
    float* Ar   = sm + 3072;      // 1536
    float* Ai   = sm + 4608;      // 1536
    float* Br   = sm + 6144;      // 1536
    float* Bi   = sm + 7680;      // 1536
    float2* tw  = (float2*)(sm + 9216);   // 768 float2 (6144 B)

    int tid = threadIdx.x;
    int bhe = blockIdx.x;
    int b = bhe >> 9;
    const float* qrow = g_qr + (size_t)bhe * LL;
    const float* krow = g_kr + (size_t)bhe * LL;

    const float TWO_PI_OVER = -6.283185307179586f / 1536.f;
    for (int t = tid; t < 768; t += 256) {
        float s, c; __sincosf(TWO_PI_OVER * (float)t, &s, &c);
        tw[t] = make_float2(c, s);
    }
    for (int i = tid; i < LL; i += 256) {
        zcr[i] = qrow[i];
        zci[i] = krow[i];
    }
    float f = g_scal[0];
    float acc0 = 0.f, acc1 = 0.f, acc2 = 0.f, acc3 = 0.f, acc4 = 0.f, acc5 = 0.f;
    __syncthreads();

    // ======== scale 1 (N=1536, M=768) ========
    fft1536_from(zcr, zci, Ar, Ai, Br, Bi, tw, tid);  // Z in B, zc preserved
    herm_split(Br, Bi, Ar, Ai, 1536, f, tid);         // R[0..768] in A
    zbuild(Ar, Ai, Br, Bi, 768, 1, tw, tid);          // z in B
    fft768(Br, Bi, Ar, Ai, tw, tid);                  // zf in A
    {
        float wgt = g_scal[1] * (1.f / 768.f);
        acc0 += wgt * cval(Ar, Ai, 768, tid);
        acc1 += wgt * cval(Ar, Ai, 768, tid + 256);
        acc2 += wgt * cval(Ar, Ai, 768, tid + 512);
        acc3 += wgt * cval(Ar, Ai, 768, tid + 768);
        acc4 += wgt * cval(Ar, Ai, 768, tid + 1024);
        acc5 += wgt * cval(Ar, Ai, 768, tid + 1280);
    }
    __syncthreads();

    // ======== scale 2 (N=768, M=384) ========
    for (int n = tid; n < 768; n += 256) {
        Ar[n] = 0.5f * (zcr[2 * n] + zcr[2 * n + 1]);
        Ai[n] = 0.5f * (zci[2 * n] + zci[2 * n + 1]);
    }
    __syncthreads();
    fft768(Ar, Ai, Br, Bi, tw, tid);                  // Z in B
    herm_split(Br, Bi, Ar, Ai, 768, f, tid);          // R[0..384] in A
    zbuild(Ar, Ai, Br, Bi, 384, 2, tw, tid);          // z in B
    fft384(Br, Bi, Ar, Ai, tw, tid);                  // zf in A
    {
        float wgt = g_scal[2] * (1.f / 384.f);
        const int N = 768;
        #pragma unroll
        for (int i = 0; i < 6; i++) {
            int l = tid + 256 * i;
            float coords = ((float)l + 0.5f) * 0.5f - 0.5f;
            coords = fminf(fmaxf(coords, 0.f), (float)(N - 1));
            int lo = (int)floorf(coords);
            int hi = min(lo + 1, N - 1);
            float fr = coords - (float)lo;
            float clo = cval(Ar, Ai, 384, lo);
            float chi = cval(Ar, Ai, 384, hi);
            float add = wgt * (clo * (1.f - fr) + chi * fr);
            if (i == 0) acc0 += add; else if (i == 1) acc1 += add;
            else if (i == 2) acc2 += add; else if (i == 3) acc3 += add;
            else if (i == 4) acc4 += add; else acc5 += add;
        }
    }
    __syncthreads();

    // ======== scale 4 (N=384, M=192) ========
    for (int n = tid; n < 384; n += 256) {
        Ar[n] = 0.25f * (zcr[4 * n] + zcr[4 * n + 1] + zcr[4 * n + 2] + zcr[4 * n + 3]);
        Ai[n] = 0.25f * (zci[4 * n] + zci[4 * n + 1] + zci[4 * n + 2] + zci[4 * n + 3]);
    }
    __syncthreads();
    fft384(Ar, Ai, Br, Bi, tw, tid);                  // Z in B
    herm_split(Br, Bi, Ar, Ai, 384, f, tid);          // R[0..192] in A
    zbuild(Ar, Ai, Br, Bi, 192, 4, tw, tid);          // z in B
    fft192(Br, Bi, Ar, Ai, tw, tid);                  // zf in B
    {
        float wgt = g_scal[3] * (1.f / 192.f);
        const int N = 384;
        #pragma unroll
        for (int i = 0; i < 6; i++) {
            int l = tid + 256 * i;
            float coords = ((float)l + 0.5f) * 0.25f - 0.5f;
            coords = fminf(fmaxf(coords, 0.f), (float)(N - 1));
            int lo = (int)floorf(coords);
            int hi = min(lo + 1, N - 1);
            float fr = coords - (float)lo;
            float clo = cval(Br, Bi, 192, lo);
            float chi = cval(Br, Bi, 192, hi);
            float add = wgt * (clo * (1.f - fr) + chi * fr);
            if (i == 0) acc0 += add; else if (i == 1) acc1 += add;
            else if (i == 2) acc2 += add; else if (i == 3) acc3 += add;
            else if (i == 4) acc4 += add; else acc5 += add;
        }
    }

    float* gm = g_mean + b * LL;
    atomicAdd(gm + tid,        fminf(fmaxf(acc0, -10.f), 10.f));
    atomicAdd(gm + tid + 256,  fminf(fmaxf(acc1, -10.f), 10.f));
    atomicAdd(gm + tid + 512,  fminf(fmaxf(acc2, -10.f), 10.f));
    atomicAdd(gm + tid + 768,  fminf(fmaxf(acc3, -10.f), 10.f));
    atomicAdd(gm + tid + 1024, fminf(fmaxf(acc4, -10.f), 10.f));
    atomicAdd(gm + tid + 1280, fminf(fmaxf(acc5, -10.f), 10.f));
}

// ---------------- K3: per-batch top-7 + softmax (single warp, shuffle-only) ----------------
__global__ __launch_bounds__(32) void k3_topk() {
    int b = blockIdx.x;
    int lane = threadIdx.x;
    float v[48];
    #pragma unroll
    for (int i = 0; i < 48; i++)
        v[i] = g_mean[b * LL + lane + 32 * i] * (1.f / HE);

    float wk[TOPK]; int dk[TOPK];
    for (int it = 0; it < TOPK; it++) {
        float best = -3.0e38f; int bi = 0;
        #pragma unroll
        for (int i = 0; i < 48; i++)
            if (v[i] > best) { best = v[i]; bi = lane + 32 * i; }
        #pragma unroll
        for (int off = 16; off; off >>= 1) {
            float ov = __shfl_down_sync(0xffffffffu, best, off);
            int   oi = __shfl_down_sync(0xffffffffu, bi,   off);
            if (ov > best || (ov == best && oi < bi)) { best = ov; bi = oi; }
        }
        best = __shfl_sync(0xffffffffu, best, 0);
        bi   = __shfl_sync(0xffffffffu, bi,   0);
        wk[it] = best; dk[it] = bi;
        if ((bi & 31) == lane) v[bi >> 5] = -3.0e38f;
    }
    if (lane == 0) {
        float mx = wk[0];
        #pragma unroll
        for (int i = 1; i < TOPK; i++) mx = fmaxf(mx, wk[i]);
        float e[TOPK], ssum = 0.f;
        #pragma unroll
        for (int i = 0; i < TOPK; i++) { e[i] = expf(wk[i] - mx); ssum += e[i]; }
        #pragma unroll
        for (int i = 0; i < TOPK; i++) {
            g_nw[b * TOPK + i] = e[i] / ssum;
            g_delays[b * TOPK + i] = dk[i];
        }
    }
}

// ---------------- K4: delayed-values aggregation ----------------
__global__ __launch_bounds__(128) void k4_out(const float* __restrict__ vals,
                                              float* __restrict__ out) {
    int bl = blockIdx.x;
    int b = bl / LL;
    int l = bl - b * LL;
    int tid = threadIdx.x;
    float nw[TOPK]; int dl[TOPK];
    #pragma unroll
    for (int k = 0; k < TOPK; k++) {
        nw[k] = g_nw[b * TOPK + k];
        dl[k] = g_delays[b * TOPK + k];
    }
    float4 acc = make_float4(0.f, 0.f, 0.f, 0.f);
    #pragma unroll
    for (int k = 0; k < TOPK; k++) {
        int ls = l + dl[k]; if (ls >= LL) ls -= LL;
        const float4* src = (const float4*)(vals + ((size_t)b * LL + ls) * HE);
        float4 v = src[tid];
        acc.x += nw[k] * v.x; acc.y += nw[k] * v.y;
        acc.z += nw[k] * v.z; acc.w += nw[k] * v.w;
    }
    ((float4*)(out + ((size_t)b * LL + l) * HE))[tid] = acc;
}

// ---------------- launch ----------------
extern "C" void kernel_launch(void* const* d_in, const int* in_sizes, int n_in,
                              void* d_out, int out_size) {
    const float* q  = (const float*)d_in[0];
    const float* kk = (const float*)d_in[1];
    const float* v  = (const float*)d_in[2];
    const float* sw = (const float*)d_in[3];
    const float* ff = (const float*)d_in[4];

    const int K2_SMEM = 43008;  // 6*1536*4 + 768*8 = 36864 + 6144

    k0_init<<<48, 256>>>(sw, ff);
    dim3 g1(48, 64, 2);
    k1_ln<<<g1, 256>>>(q, kk);
    k2_corr<<<BHE, 256, K2_SMEM>>>();
    k3_topk<<<BB, 32>>>();
    k4_out<<<BB * LL, 128>>>(v, (float*)d_out);
}